// round 13
// baseline (speedup 1.0000x reference)
#include <cuda_runtime.h>
#include <cuda_bf16.h>
#include <cstdint>

#define OUT_SZ 7
#define NCELL (OUT_SZ * OUT_SZ)      // 49
#define NCH 256
#define NLANE 32                     // lanes per row; each lane = 8 channels
#define NTHREADS (NLANE * OUT_SZ)    // 224: slot = output row, 32 lanes

// level thresholds on wh = roi_h*roi_w:
//   level >= c  <=>  wh >= 224^2 * 2^(2*(c-4)),  c = 2.5, 3.5, 4.5
#define T3 6272.0f      // 224^2 / 8
#define T4 25088.0f     // 224^2 / 2
#define T5 100352.0f    // 224^2 * 2

struct F8 { float v[8]; };

__device__ __forceinline__ F8 ldg256(const float* p) {
    F8 r;
    asm volatile("ld.global.nc.v8.f32 {%0,%1,%2,%3,%4,%5,%6,%7}, [%8];"
        : "=f"(r.v[0]), "=f"(r.v[1]), "=f"(r.v[2]), "=f"(r.v[3]),
          "=f"(r.v[4]), "=f"(r.v[5]), "=f"(r.v[6]), "=f"(r.v[7])
        : "l"(p));
    return r;
}

__device__ __forceinline__ void stg256_cs(float* p, const F8& r) {
    asm volatile("st.global.cs.v8.f32 [%0], {%1,%2,%3,%4,%5,%6,%7,%8};"
        :: "l"(p),
           "f"(r.v[0]), "f"(r.v[1]), "f"(r.v[2]), "f"(r.v[3]),
           "f"(r.v[4]), "f"(r.v[5]), "f"(r.v[6]), "f"(r.v[7])
        : "memory");
}

__global__ __launch_bounds__(NTHREADS)
void roialign_kernel(const float* __restrict__ p2,
                     const float* __restrict__ p3,
                     const float* __restrict__ p4,
                     const float* __restrict__ p5,
                     const float* __restrict__ rois,
                     float* __restrict__ out)
{
    int roi  = blockIdx.x;
    int tid  = threadIdx.x;
    int lane = tid & (NLANE - 1);    // channel octet 0..31
    int i    = tid >> 5;             // output row 0..6
    int ch8  = lane * 8;             // channel offset (floats)

    // ---- cheap per-thread ROI decode (no MUFU), amortized over 7 cells ----
    const float* r = rois + (size_t)roi * 5;   // [batch, x1, y1, x2, y2]
    float bf  = __ldg(r + 0);
    float rx1 = __ldg(r + 1), ry1 = __ldg(r + 2);
    float rx2 = __ldg(r + 3), ry2 = __ldg(r + 4);
    int b = (int)bf;

    float dx = rx2 - rx1;            // roi_w
    float dy = ry2 - ry1;            // roi_h
    float wh = dy * dx;
    int level = 2 + (wh >= T3) + (wh >= T4) + (wh >= T5);

    const float* fm = level < 4 ? (level == 2 ? p2 : p3)
                                : (level == 4 ? p4 : p5);
    // c = (H-1) * 2^-level, selected per level
    float c = level < 4 ? (level == 2 ? 63.75f   : 15.875f)
                        : (level == 4 ? 3.9375f  : 0.96875f);
    float c6 = c * (1.0f / 6.0f);
    int   Hm1i = (1024 >> level) - 1;
    float Hm1  = (float)Hm1i;
    int   rowstride = 262144 >> level;         // H * NCH (float units)

    // crop_and_resize reads boxes as [y1,x1,y2,x2]; roi_align passes
    // [x1,y1,x2,y2]*(1/stride). So the crop's y-axis uses rx, x-axis uses ry.
    float y_base  = rx1 * c;
    float x_base  = ry1 * c;
    float h_scale = dx * c6;
    float w_scale = dy * c6;

    const float* fm_b = fm + ((size_t)b << (28 - 2 * level));
    float* out_row = out + (size_t)roi * NCELL * NCH + i * OUT_SZ * NCH + ch8;

    // ---- y-axis (hoisted: shared by the whole output row) ----
    float in_y = fmaf((float)i, h_scale, y_base);
    bool  vy   = (in_y >= 0.0f) & (in_y <= Hm1);

    F8 zero;
#pragma unroll
    for (int k = 0; k < 8; k++) zero.v[k] = 0.0f;

    if (!vy) {
#pragma unroll
        for (int j = 0; j < OUT_SZ; j++)
            stg256_cs(out_row + j * NCH, zero);
        return;
    }

    float fy = floorf(in_y);
    float ly = in_y - fy;
    int   y0 = (int)fy;                               // valid ⇒ in [0, Hm1i]
    int   yc = (int)fminf(ceilf(in_y), Hm1);
    const float* r0 = fm_b + (size_t)y0 * rowstride + ch8;
    const float* r1 = fm_b + (size_t)yc * rowstride + ch8;

#pragma unroll 2
    for (int j = 0; j < OUT_SZ; j++) {
        float in_x = fmaf((float)j, w_scale, x_base);
        bool  vx   = (in_x >= 0.0f) & (in_x <= Hm1);  // warp-uniform
        F8 v = zero;
        if (vx) {
            float fx = floorf(in_x);
            float lx = in_x - fx;
            int x0 = (int)fx;                         // valid ⇒ in [0, Hm1i]
            int xc = (int)fminf(ceilf(in_x), Hm1);
            F8 tl = ldg256(r0 + x0 * NCH);
            F8 tr = ldg256(r0 + xc * NCH);
            F8 bl = ldg256(r1 + x0 * NCH);
            F8 br = ldg256(r1 + xc * NCH);
#pragma unroll
            for (int k = 0; k < 8; k++) {
                float top = fmaf(tr.v[k] - tl.v[k], lx, tl.v[k]);
                float bot = fmaf(br.v[k] - bl.v[k], lx, bl.v[k]);
                v.v[k] = fmaf(bot - top, ly, top);
            }
        }
        stg256_cs(out_row + j * NCH, v);
    }
}

extern "C" void kernel_launch(void* const* d_in, const int* in_sizes, int n_in,
                              void* d_out, int out_size)
{
    const float* p2   = (const float*)d_in[0];
    const float* p3   = (const float*)d_in[1];
    const float* p4   = (const float*)d_in[2];
    const float* p5   = (const float*)d_in[3];
    const float* rois = (const float*)d_in[4];
    float* out = (float*)d_out;
    int n_rois = in_sizes[4] / 5;

    roialign_kernel<<<n_rois, NTHREADS>>>(p2, p3, p4, p5, rois, out);
}

// round 14
// speedup vs baseline: 1.0310x; 1.0310x over previous
#include <cuda_runtime.h>
#include <cuda_bf16.h>

#define OUT_SZ 7
#define NCELL (OUT_SZ * OUT_SZ)      // 49
#define NCH 256
#define NQ (NCH / 4)                 // 64 float4 per channel row
#define NTHREADS 256
#define ROI_F4 (NCELL * NCH / 4)     // 3136 float4 per ROI

// level thresholds on wh = roi_h*roi_w:
//   level >= c  <=>  wh >= 224^2 * 2^(2*(c-4)),  c = 2.5, 3.5, 4.5
#define T3 6272.0f      // 224^2 / 8
#define T4 25088.0f     // 224^2 / 2
#define T5 100352.0f    // 224^2 * 2

__global__ __launch_bounds__(NTHREADS, 8)
void roialign_kernel(const float* __restrict__ p2,
                     const float* __restrict__ p3,
                     const float* __restrict__ p4,
                     const float* __restrict__ p5,
                     const float* __restrict__ rois,
                     float* __restrict__ out)
{
    int roi = blockIdx.x;
    int tid = threadIdx.x;

    // ---- cheap per-thread ROI decode (no MUFU) ----
    const float* r = rois + (size_t)roi * 5;   // [batch, x1, y1, x2, y2]
    float bf  = __ldg(r + 0);
    float rx1 = __ldg(r + 1), ry1 = __ldg(r + 2);
    float rx2 = __ldg(r + 3), ry2 = __ldg(r + 4);
    int b = (int)bf;

    float dx = rx2 - rx1;            // roi_w
    float dy = ry2 - ry1;            // roi_h
    float wh = dy * dx;
    int level = 2 + (wh >= T3) + (wh >= T4) + (wh >= T5);

    // c = (H-1) * 2^-level, selected per level
    float c = level < 4 ? (level == 2 ? 63.75f   : 15.875f)
                        : (level == 4 ? 3.9375f  : 0.96875f);
    int   Hm1i = (1024 >> level) - 1;
    float Hm1  = (float)Hm1i;

    // crop_and_resize reads boxes as [y1,x1,y2,x2]; roi_align passes
    // [x1,y1,x2,y2]*(1/stride). So the crop's y-axis uses rx, x-axis uses ry.
    float y_base = rx1 * c;
    float x_base = ry1 * c;

    float4* out_f4 = (float4*)(out + (size_t)roi * NCELL * NCH);

    // Any valid cell exists iff cell (0,0) is valid: in_y(i), in_x(j) are
    // nonneg & nondecreasing in i,j, so (0,0) is the minimum. Same rounding
    // as the full path => bit-exact split.
    bool any_valid = (y_base <= Hm1) & (x_base <= Hm1);

    if (!any_valid) {
        // ---- fast path (~99% of ROIs): pure zero-fill, 3136 float4 ----
        float4 zero = make_float4(0.f, 0.f, 0.f, 0.f);
#pragma unroll
        for (int k = 0; k < 13; k++) {
            int idx = k * NTHREADS + tid;
            if (k < 12 || idx < ROI_F4)      // 3136 = 12*256 + 64
                out_f4[idx] = zero;
        }
        return;
    }

    // ---- full path (rare): 4 row-slots x 64 channel quads ----
    const float* fm = level < 4 ? (level == 2 ? p2 : p3)
                                : (level == 4 ? p4 : p5);
    float c6 = c * (1.0f / 6.0f);
    int   rowstride = 65536 >> level;          // H * NQ (float4 units)
    float h_scale = dx * c6;
    float w_scale = dy * c6;

    const float4* fm_b = (const float4*)(fm + ((size_t)b << (28 - 2 * level)));

    int cq   = tid & (NQ - 1);       // channel quad 0..63
    int slot = tid >> 6;             // 0..3
    float4 zero = make_float4(0.f, 0.f, 0.f, 0.f);

#pragma unroll 1
    for (int i = slot; i < OUT_SZ; i += 4) {
        float4* out_row = out_f4 + i * OUT_SZ * NQ + cq;

        float in_y = fmaf((float)i, h_scale, y_base);
        bool  vy   = (in_y >= 0.0f) & (in_y <= Hm1);

        if (!vy) {
#pragma unroll
            for (int j = 0; j < OUT_SZ; j++)
                out_row[j * NQ] = zero;
            continue;
        }

        float fy = floorf(in_y);
        float ly = in_y - fy;
        int   y0 = (int)fy;                           // valid => in [0, Hm1i]
        int   yc = (int)fminf(ceilf(in_y), Hm1);
        const float4* r0 = fm_b + y0 * rowstride;
        const float4* r1 = fm_b + yc * rowstride;

#pragma unroll 2
        for (int j = 0; j < OUT_SZ; j++) {
            float in_x = fmaf((float)j, w_scale, x_base);
            bool  vx   = (in_x >= 0.0f) & (in_x <= Hm1);
            float4 v = zero;
            if (vx) {
                float fx = floorf(in_x);
                float lx = in_x - fx;
                int x0 = (int)fx;                     // valid => in [0, Hm1i]
                int xc = (int)fminf(ceilf(in_x), Hm1);
                float4 tl = __ldg(r0 + x0 * NQ + cq);
                float4 tr = __ldg(r0 + xc * NQ + cq);
                float4 bl = __ldg(r1 + x0 * NQ + cq);
                float4 br = __ldg(r1 + xc * NQ + cq);

                float4 top, bot;
                top.x = fmaf(tr.x - tl.x, lx, tl.x);
                top.y = fmaf(tr.y - tl.y, lx, tl.y);
                top.z = fmaf(tr.z - tl.z, lx, tl.z);
                top.w = fmaf(tr.w - tl.w, lx, tl.w);
                bot.x = fmaf(br.x - bl.x, lx, bl.x);
                bot.y = fmaf(br.y - bl.y, lx, bl.y);
                bot.z = fmaf(br.z - bl.z, lx, bl.z);
                bot.w = fmaf(br.w - bl.w, lx, bl.w);
                v.x = fmaf(bot.x - top.x, ly, top.x);
                v.y = fmaf(bot.y - top.y, ly, top.y);
                v.z = fmaf(bot.z - top.z, ly, top.z);
                v.w = fmaf(bot.w - top.w, ly, top.w);
            }
            out_row[j * NQ] = v;
        }
    }
}

extern "C" void kernel_launch(void* const* d_in, const int* in_sizes, int n_in,
                              void* d_out, int out_size)
{
    const float* p2   = (const float*)d_in[0];
    const float* p3   = (const float*)d_in[1];
    const float* p4   = (const float*)d_in[2];
    const float* p5   = (const float*)d_in[3];
    const float* rois = (const float*)d_in[4];
    float* out = (float*)d_out;
    int n_rois = in_sizes[4] / 5;

    roialign_kernel<<<n_rois, NTHREADS>>>(p2, p3, p4, p5, rois, out);
}